// round 1
// baseline (speedup 1.0000x reference)
#include <cuda_runtime.h>
#include <math.h>

#define NFEAT 4096
#define BATCH 128

// Scratch (device globals; no runtime allocation)
__device__ float g_xf[BATCH * NFEAT];        // folded input      [128, 4096]
__device__ float g_h0[BATCH * 2 * NFEAT];    // layer0 output     [128, 8192]
__device__ float g_h1[BATCH * 2 * NFEAT];    // layer1 output     [128, 8192]

// ---------------------------------------------------------------------------
// Closed-form fold permutation: folded index j -> flat site index (row*64+col)
// Matches the python quad-tree construction exactly.
// ---------------------------------------------------------------------------
__device__ __forceinline__ int perm_site(int j) {
    if (j == 0) return 0;
    int m = (31 - __clz((unsigned)j)) >> 1;   // floor(log4 j)
    int q = j >> (2 * m);                     // 1,2,3 (sublattice)
    int t = j - (q << (2 * m));
    int ri = t >> m;
    int ci = t & ((1 << m) - 1);
    int s = 1 << (5 - m);
    int p = s << 1;
    int row, col;
    if (q == 1)      { row = s + ri * p; col = s + ci * p; }
    else if (q == 2) { row = s + ri * p; col = ci * p;     }
    else             { row = ri * p;     col = s + ci * p; }
    return (row << 6) + col;
}

// Level groups are contiguous & monotone in folded index:
// group of j is [g*4^m, (g+1)*4^m). Inclusive mask => cols < grp_end(r),
// exclusive mask => cols < grp_start(r).
__device__ __forceinline__ int grp_start(int j) {
    if (j == 0) return 0;
    int m = (31 - __clz((unsigned)j)) >> 1;
    return (j >> (2 * m)) << (2 * m);
}
__device__ __forceinline__ int grp_end(int j) {
    if (j == 0) return 1;
    int m = (31 - __clz((unsigned)j)) >> 1;
    return ((j >> (2 * m)) + 1) << (2 * m);
}

// ---------------------------------------------------------------------------
// Input fold gather: xf[b, j] = x[b, perm_site(j)]
// ---------------------------------------------------------------------------
__global__ void gather_kernel(const float* __restrict__ x) {
    int idx = blockIdx.x * blockDim.x + threadIdx.x;   // over 128*4096
    int j = idx & (NFEAT - 1);
    int b = idx >> 12;
    g_xf[idx] = x[(b << 12) + perm_site(j)];
}

// ---------------------------------------------------------------------------
// Masked GEMM: out[b, r] = epi( sum_c X[b,c] * W[r,c] * mask(r,c) + bias[r] )
// mask(r,c): (c mod NFEAT) < cutoff(r mod NFEAT), per 4096-col half.
// Tile: 128 batch x 32 rows, TK=32. 256 threads, 8x2 micro-tile per thread.
// SEL: 0 -> X=g_xf,out=g_h0 ; 1 -> X=g_h0,out=g_h1 ; 2 -> X=g_h1,out=param
// EPI: 0 -> bias+PReLU(alpha) ; 1 -> bias+sigmoid+xhat-mask+scatter by PERM
// ---------------------------------------------------------------------------
template<int HALVES, bool EXCL, int EPI, int SEL>
__global__ __launch_bounds__(256)
void gemm_kernel(const float* __restrict__ W,
                 const float* __restrict__ bias,
                 const float* __restrict__ alpha,
                 float* __restrict__ outp, int R)
{
    const int C = HALVES * NFEAT;
    const float* X = (SEL == 0) ? g_xf : (SEL == 1) ? g_h0 : g_h1;
    float* out     = (SEL == 0) ? g_h0 : (SEL == 1) ? g_h1 : outp;

    __shared__ float Xs[32][128];   // k-major, xor-swizzled in batch dim
    __shared__ float Ws[32][32];    // k-major, xor-swizzled in row dim
    __shared__ int cut_s[32];

    const int r0 = blockIdx.x * 32;
    const int t  = threadIdx.x;
    const int tx = t & 15;          // batch group  (8 rows each)
    const int ty = t >> 4;          // weight-row group (2 each)
    const int b0  = tx << 3;
    const int rr0 = ty << 1;

    if (t < 32) {
        int rmod = (r0 + t) & (NFEAT - 1);
        cut_s[t] = EXCL ? grp_start(rmod) : grp_end(rmod);
    }
    __syncthreads();
    const int Kmax = cut_s[31];     // cutoffs monotone within tile

    float acc[8][2];
#pragma unroll
    for (int i = 0; i < 8; i++) { acc[i][0] = 0.f; acc[i][1] = 0.f; }

    for (int h = 0; h < HALVES; h++) {
        const float* Xh = X + h * NFEAT;
        const float* Wh = W + h * NFEAT;
        for (int k0 = 0; k0 < Kmax; k0 += 32) {
            // ---- load X tile [128 x 32] (4 float4 per thread), transpose+swizzle
#pragma unroll
            for (int l = 0; l < 4; l++) {
                int f   = t + l * 256;          // 0..1023
                int b   = f >> 3;               // 0..127
                int kk4 = f & 7;                // float4 index in k
                float4 v = *(const float4*)(Xh + (size_t)b * C + k0 + kk4 * 4);
                int bp = b ^ ((kk4 & 3) << 3);  // swizzle: s = ((k>>2)&3)<<3
                Xs[kk4 * 4 + 0][bp] = v.x;
                Xs[kk4 * 4 + 1][bp] = v.y;
                Xs[kk4 * 4 + 2][bp] = v.z;
                Xs[kk4 * 4 + 3][bp] = v.w;
            }
            // ---- load W tile [32 x 32] with mask (1 float4 per thread)
            {
                int rr  = t >> 3;               // 0..31
                int kk4 = t & 7;
                int cb  = k0 + kk4 * 4;
                int cut = cut_s[rr];
                float4 v = *(const float4*)(Wh + (size_t)(r0 + rr) * C + cb);
                int rp = rr ^ ((kk4 & 3) << 3);
                Ws[kk4 * 4 + 0][rp] = (cb + 0 < cut) ? v.x : 0.f;
                Ws[kk4 * 4 + 1][rp] = (cb + 1 < cut) ? v.y : 0.f;
                Ws[kk4 * 4 + 2][rp] = (cb + 2 < cut) ? v.z : 0.f;
                Ws[kk4 * 4 + 3][rp] = (cb + 3 < cut) ? v.w : 0.f;
            }
            __syncthreads();
#pragma unroll 4
            for (int k = 0; k < 32; k++) {
                int sw = ((k >> 2) & 3) << 3;
                const float4* xp = (const float4*)&Xs[k][b0 ^ sw];
                float4 xA = xp[0];
                float4 xB = xp[1];
                const float2 wv = *(const float2*)&Ws[k][rr0 ^ sw];
                float xv[8] = {xA.x, xA.y, xA.z, xA.w, xB.x, xB.y, xB.z, xB.w};
#pragma unroll
                for (int i = 0; i < 8; i++) {
                    acc[i][0] = fmaf(xv[i], wv.x, acc[i][0]);
                    acc[i][1] = fmaf(xv[i], wv.y, acc[i][1]);
                }
            }
            __syncthreads();
        }
    }

    // ---- fused epilogue
#pragma unroll
    for (int j = 0; j < 2; j++) {
        int r = r0 + rr0 + j;
        float bv = bias[r];
        if (EPI == 0) {
            float av = alpha[r];
#pragma unroll
            for (int i = 0; i < 8; i++) {
                float v = acc[i][j] + bv;
                out[(size_t)(b0 + i) * R + r] = (v > 0.f) ? v : av * v;
            }
        } else {
            int site = perm_site(r);   // scatter: unfold via PERM
#pragma unroll
            for (int i = 0; i < 8; i++) {
                float v = acc[i][j] + bv;
                float sg = (r == 0) ? 0.5f : 1.f / (1.f + expf(-v));
                out[(size_t)(b0 + i) * NFEAT + site] = sg;
            }
        }
    }
}

// ---------------------------------------------------------------------------
// Inputs (metadata order): x, W0, b0, a1, W1, b1, a2, W2, b2. Output: f32 [128,64,64]
// ---------------------------------------------------------------------------
extern "C" void kernel_launch(void* const* d_in, const int* in_sizes, int n_in,
                              void* d_out, int out_size) {
    const float* x  = (const float*)d_in[0];
    const float* W0 = (const float*)d_in[1];
    const float* b0 = (const float*)d_in[2];
    const float* a1 = (const float*)d_in[3];
    const float* W1 = (const float*)d_in[4];
    const float* b1 = (const float*)d_in[5];
    const float* a2 = (const float*)d_in[6];
    const float* W2 = (const float*)d_in[7];
    const float* b2 = (const float*)d_in[8];
    float* out = (float*)d_out;

    gather_kernel<<<(BATCH * NFEAT) / 256, 256>>>(x);

    // L0: exclusive mask, 1 column half, PReLU(a1)  -> g_h0 [128,8192]
    gemm_kernel<1, true, 0, 0><<<(2 * NFEAT) / 32, 256>>>(W0, b0, a1, nullptr, 2 * NFEAT);
    // L1: inclusive mask, 2 column halves, PReLU(a2) -> g_h1 [128,8192]
    gemm_kernel<2, false, 0, 1><<<(2 * NFEAT) / 32, 256>>>(W1, b1, a2, nullptr, 2 * NFEAT);
    // L2: inclusive mask, 2 halves, sigmoid + xhat mask/bias + unfold scatter
    gemm_kernel<2, false, 1, 2><<<NFEAT / 32, 256>>>(W2, b2, nullptr, out, NFEAT);
}

// round 3
// speedup vs baseline: 6.7202x; 6.7202x over previous
#include <cuda_runtime.h>
#include <cuda_fp16.h>
#include <math.h>
#include <stdint.h>

#define NFEAT 4096
#define BATCH 128

// ---------------- device scratch (static; no runtime allocation) -------------
__device__ float4 g_xh_raw[BATCH * NFEAT / 8];        // half [128, 4096] folded x
__device__ float4 g_act0_raw[BATCH * 2 * NFEAT / 8];  // half [128, 8192] layer0 out
__device__ float4 g_act1_raw[BATCH * 2 * NFEAT / 8];  // half [128, 8192] layer1 out

// ---------------- closed-form fold / mask helpers ----------------------------
__device__ __forceinline__ int perm_site(int j) {
    if (j == 0) return 0;
    int m = (31 - __clz((unsigned)j)) >> 1;   // floor(log4 j)
    int q = j >> (2 * m);
    int t = j - (q << (2 * m));
    int ri = t >> m;
    int ci = t & ((1 << m) - 1);
    int s = 1 << (5 - m);
    int p = s << 1;
    int row, col;
    if (q == 1)      { row = s + ri * p; col = s + ci * p; }
    else if (q == 2) { row = s + ri * p; col = ci * p;     }
    else             { row = ri * p;     col = s + ci * p; }
    return (row << 6) + col;
}
__device__ __forceinline__ int grp_start(int j) {
    if (j == 0) return 0;
    int m = (31 - __clz((unsigned)j)) >> 1;
    return (j >> (2 * m)) << (2 * m);
}
__device__ __forceinline__ int grp_end(int j) {
    if (j == 0) return 1;
    int m = (31 - __clz((unsigned)j)) >> 1;
    return ((j >> (2 * m)) + 1) << (2 * m);
}

// ---------------- small PTX helpers -------------------------------------------
__device__ __forceinline__ uint32_t smem_u32(const void* p) {
    uint32_t a;
    asm("{ .reg .u64 t; cvta.to.shared.u64 t, %1; cvt.u32.u64 %0, t; }" : "=r"(a) : "l"(p));
    return a;
}
#define SWZ(o) ((o) ^ (((o) >> 3) & 0x70))

__device__ __forceinline__ void cp_async16(uint32_t dst, const void* src) {
    asm volatile("cp.async.cg.shared.global [%0], [%1], 16;" :: "r"(dst), "l"(src) : "memory");
}
__device__ __forceinline__ void cp_commit() {
    asm volatile("cp.async.commit_group;" ::: "memory");
}
template<int N>
__device__ __forceinline__ void cp_wait() {
    asm volatile("cp.async.wait_group %0;" :: "n"(N) : "memory");
}
__device__ __forceinline__ void ldm_x4(uint32_t addr, uint32_t& r0, uint32_t& r1,
                                       uint32_t& r2, uint32_t& r3) {
    asm volatile("ldmatrix.sync.aligned.m8n8.x4.shared.b16 {%0,%1,%2,%3}, [%4];"
                 : "=r"(r0), "=r"(r1), "=r"(r2), "=r"(r3) : "r"(addr));
}
__device__ __forceinline__ void mma16816(float* c, uint32_t a0, uint32_t a1, uint32_t a2,
                                         uint32_t a3, uint32_t b0, uint32_t b1) {
    asm volatile("mma.sync.aligned.m16n8k16.row.col.f32.f16.f16.f32 "
                 "{%0,%1,%2,%3},{%4,%5,%6,%7},{%8,%9},{%0,%1,%2,%3};"
                 : "+f"(c[0]), "+f"(c[1]), "+f"(c[2]), "+f"(c[3])
                 : "r"(a0), "r"(a1), "r"(a2), "r"(a3), "r"(b0), "r"(b1));
}

// ---------------- gather: fold input to fp16 ----------------------------------
__global__ void gather_kernel(const float* __restrict__ x) {
    int idx = blockIdx.x * blockDim.x + threadIdx.x;   // 128*4096
    int j = idx & (NFEAT - 1);
    int b = idx >> 12;
    ((half*)g_xh_raw)[idx] = __float2half_rn(x[(b << 12) + perm_site(j)]);
}

// ---------------- masked GEMM via mma.sync -------------------------------------
// D[m, r0+n] = sum_c X[m,c] * W[r0+n,c]  (per-row contiguous cutoff mask)
// M = 128 (batch), N-tile = 32 weight rows/CTA, K-stage = 64 fp16.
// 256 threads = 8 warps; each warp owns m16 (wid*16) x n32; 4 k16 steps/stage.
// SMEM (dynamic): [0..128) cut_s[32]; A: 2x16KB @1024; B: 2x4KB @33792.
#define OFF_A 1024
#define OFF_B (1024 + 32768)
#define SMEM_TOTAL (1024 + 32768 + 8192)

template<int HALVES, bool EXCL, int EPI, int SEL>
__global__ __launch_bounds__(256)
void mma_kernel(const float* __restrict__ W,
                const float* __restrict__ bias,
                const float* __restrict__ alpha,
                float* __restrict__ outp)
{
    extern __shared__ __align__(1024) char smem[];
    const uint32_t smem_base = smem_u32(smem);
    const int t = threadIdx.x;
    const int wid = t >> 5, lane = t & 31;
    const int C = (SEL == 0) ? NFEAT : 2 * NFEAT;
    const half* Asrc = (SEL == 0) ? (const half*)g_xh_raw
                     : (SEL == 1) ? (const half*)g_act0_raw
                                  : (const half*)g_act1_raw;
    half* actout = (SEL == 0) ? (half*)g_act0_raw : (half*)g_act1_raw;
    const int r0 = blockIdx.x * 32;

    int* cut_s = (int*)smem;
    if (t < 32) {
        int rmod = (r0 + t) & (NFEAT - 1);
        cut_s[t] = EXCL ? grp_start(rmod) : grp_end(rmod);
    }
    __syncthreads();

    const int Kmax = cut_s[31];               // cutoffs monotone within tile
    const int nk = (Kmax + 63) >> 6;          // K-stages per 4096-half
    const int S = HALVES * nk;

    // W-load lane mapping: fid = t + l*256 (l<2): n = fid>>4, c4 = fid&15
    const int wl_n[2]  = { t >> 4, (t + 256) >> 4 };
    const int wl_c4[2] = { t & 15, t & 15 };

    // producer: async-copy A tile for stage s into buffer b
    auto cp_a = [&](int s, int b) {
        int hh = s / nk, kk = s - hh * nk;
        const half* Ah = Asrc + hh * NFEAT + (kk << 6);
        uint32_t Ab = smem_base + OFF_A + b * 16384;
#pragma unroll
        for (int l = 0; l < 4; l++) {
            int fid = t + l * 256;
            int m = fid >> 3, c16 = fid & 7;
            cp_async16(Ab + SWZ(m * 128 + c16 * 16), Ah + (size_t)m * C + c16 * 8);
        }
        cp_commit();
    };
    // producer: global->reg masked W load for stage s
    auto ldg_w = [&](int s, float4* wr) {
        int hh = s / nk, kk = s - hh * nk;
        int k0 = kk << 6;
        const float* Wh = W + hh * NFEAT;
#pragma unroll
        for (int l = 0; l < 2; l++) {
            int n = wl_n[l], c4 = wl_c4[l];
            int ke = k0 + c4 * 4;
            int cut = cut_s[n];
            float4 v = make_float4(0.f, 0.f, 0.f, 0.f);
            if (ke < cut) v = *(const float4*)(Wh + (size_t)(r0 + n) * C + ke);
            if (ke + 1 >= cut) v.y = 0.f;
            if (ke + 2 >= cut) v.z = 0.f;
            if (ke + 3 >= cut) v.w = 0.f;
            wr[l] = v;
        }
    };
    auto sts_w = [&](const float4* wr, int b) {
        uint32_t Bb = smem_base + OFF_B + b * 4096;
#pragma unroll
        for (int l = 0; l < 2; l++) {
            int n = wl_n[l], c4 = wl_c4[l];
            half2 lo = __floats2half2_rn(wr[l].x, wr[l].y);
            half2 hi = __floats2half2_rn(wr[l].z, wr[l].w);
            uint2 pk;
            pk.x = *(uint32_t*)&lo;
            pk.y = *(uint32_t*)&hi;
            *(uint2*)((char*)smem + (Bb - smem_base) + 0) = pk;  // placeholder (replaced below)
        }
    };
    (void)sts_w; // not used; inlined below for correct swizzled addresses

    float acc[4][4];
#pragma unroll
    for (int i = 0; i < 4; i++)
#pragma unroll
        for (int j = 0; j < 4; j++) acc[i][j] = 0.f;

    // ldmatrix per-lane geometry
    const int rowA = wid * 16 + (lane & 15);
    const int rowB = lane & 15;
    const int colHi = (lane >> 4) * 8;     // 0 or 8 (k within 16)

    float4 wreg[2];
    if (S > 0) {
        ldg_w(0, wreg);
        cp_a(0, 0);
    }

    for (int s = 0; s < S; s++) {
        const int b = s & 1;
        // store W regs (stage s) into SMEM buffer b
        {
            uint32_t Bb = smem_base + OFF_B + b * 4096;
#pragma unroll
            for (int l = 0; l < 2; l++) {
                int n = wl_n[l], c4 = wl_c4[l];
                half2 lo = __floats2half2_rn(wreg[l].x, wreg[l].y);
                half2 hi = __floats2half2_rn(wreg[l].z, wreg[l].w);
                uint2 pk;
                pk.x = *(uint32_t*)&lo;
                pk.y = *(uint32_t*)&hi;
                *(uint2*)(smem + (Bb - smem_base) + SWZ(n * 128 + c4 * 8)) = pk;
            }
        }
        if (s + 1 < S) {
            cp_a(s + 1, b ^ 1);   // prefetch next A
            cp_wait<1>();         // stage-s A group complete
        } else {
            cp_wait<0>();
        }
        __syncthreads();
        if (s + 1 < S) ldg_w(s + 1, wreg);   // overlap next W LDG with MMA

        const uint32_t Ab = smem_base + OFF_A + b * 16384;
        const uint32_t Bb = smem_base + OFF_B + b * 4096;
#pragma unroll
        for (int kk = 0; kk < 4; kk++) {
            const int kc = kk * 16 + colHi;
            uint32_t a0, a1, a2, a3, p0, p1, p2, p3, q0, q1, q2, q3;
            ldm_x4(Ab + SWZ(rowA * 128 + kc * 2), a0, a1, a2, a3);
            ldm_x4(Bb + SWZ(rowB * 128 + kc * 2), p0, p1, p2, p3);
            ldm_x4(Bb + SWZ((rowB + 16) * 128 + kc * 2), q0, q1, q2, q3);
            mma16816(acc[0], a0, a1, a2, a3, p0, p2);
            mma16816(acc[1], a0, a1, a2, a3, p1, p3);
            mma16816(acc[2], a0, a1, a2, a3, q0, q2);
            mma16816(acc[3], a0, a1, a2, a3, q1, q3);
        }
        __syncthreads();
    }

    // ---- fused epilogue (registers -> global)
    const int m = wid * 16 + (lane >> 2);      // rows m and m+8
#pragma unroll
    for (int ni = 0; ni < 4; ni++) {
        int r = r0 + ni * 8 + (lane & 3) * 2;
        if (EPI == 0) {
            float bx = __ldg(bias + r), by = __ldg(bias + r + 1);
            float ax = __ldg(alpha + r), ay = __ldg(alpha + r + 1);
            float v0 = acc[ni][0] + bx, v1 = acc[ni][1] + by;
            float v2 = acc[ni][2] + bx, v3 = acc[ni][3] + by;
            v0 = (v0 > 0.f) ? v0 : ax * v0;
            v1 = (v1 > 0.f) ? v1 : ay * v1;
            v2 = (v2 > 0.f) ? v2 : ax * v2;
            v3 = (v3 > 0.f) ? v3 : ay * v3;
            *(half2*)(actout + (size_t)m * (2 * NFEAT) + r) = __floats2half2_rn(v0, v1);
            *(half2*)(actout + (size_t)(m + 8) * (2 * NFEAT) + r) = __floats2half2_rn(v2, v3);
        } else {
            float bx = __ldg(bias + r), by = __ldg(bias + r + 1);
            int s0 = perm_site(r), s1 = perm_site(r + 1);
            float v0 = acc[ni][0] + bx, v1 = acc[ni][1] + by;
            float v2 = acc[ni][2] + bx, v3 = acc[ni][3] + by;
            float g0 = (r == 0) ? 0.5f : 1.f / (1.f + __expf(-v0));
            float g2 = (r == 0) ? 0.5f : 1.f / (1.f + __expf(-v2));
            float g1 = 1.f / (1.f + __expf(-v1));
            float g3 = 1.f / (1.f + __expf(-v3));
            outp[(size_t)m * NFEAT + s0] = g0;
            outp[(size_t)m * NFEAT + s1] = g1;
            outp[(size_t)(m + 8) * NFEAT + s0] = g2;
            outp[(size_t)(m + 8) * NFEAT + s1] = g3;
        }
    }
}

// ---------------- launcher ------------------------------------------------------
extern "C" void kernel_launch(void* const* d_in, const int* in_sizes, int n_in,
                              void* d_out, int out_size) {
    const float* x  = (const float*)d_in[0];
    const float* W0 = (const float*)d_in[1];
    const float* b0 = (const float*)d_in[2];
    const float* a1 = (const float*)d_in[3];
    const float* W1 = (const float*)d_in[4];
    const float* b1 = (const float*)d_in[5];
    const float* a2 = (const float*)d_in[6];
    const float* W2 = (const float*)d_in[7];
    const float* b2 = (const float*)d_in[8];
    float* out = (float*)d_out;

    gather_kernel<<<(BATCH * NFEAT) / 256, 256>>>(x);

    // L0: exclusive mask, C=4096, PReLU(a1) -> g_act0 [128, 8192]
    mma_kernel<1, true,  0, 0><<<256, 256, SMEM_TOTAL>>>(W0, b0, a1, nullptr);
    // L1: inclusive mask, C=8192, PReLU(a2) -> g_act1 [128, 8192]
    mma_kernel<2, false, 0, 1><<<256, 256, SMEM_TOTAL>>>(W1, b1, a2, nullptr);
    // L2: inclusive mask, C=8192, sigmoid + xhat mask/bias + unfold scatter
    mma_kernel<2, false, 1, 2><<<128, 256, SMEM_TOTAL>>>(W2, b2, nullptr, out);
}

// round 4
// speedup vs baseline: 9.2113x; 1.3707x over previous
#include <cuda_runtime.h>
#include <cuda_fp16.h>
#include <math.h>
#include <stdint.h>

#define NFEAT 4096
#define BATCH 128

// ---------------- device scratch (static; no runtime allocation) -------------
__device__ float4 g_xh_raw[BATCH * NFEAT / 8];        // half [128, 4096] folded x
__device__ float4 g_act0_raw[BATCH * 2 * NFEAT / 8];  // half [128, 8192] layer0 out
__device__ float4 g_act1_raw[BATCH * 2 * NFEAT / 8];  // half [128, 8192] layer1 out

// ---------------- closed-form fold / mask helpers ----------------------------
__device__ __forceinline__ int perm_site(int j) {
    if (j == 0) return 0;
    int m = (31 - __clz((unsigned)j)) >> 1;   // floor(log4 j)
    int q = j >> (2 * m);
    int t = j - (q << (2 * m));
    int ri = t >> m;
    int ci = t & ((1 << m) - 1);
    int s = 1 << (5 - m);
    int p = s << 1;
    int row, col;
    if (q == 1)      { row = s + ri * p; col = s + ci * p; }
    else if (q == 2) { row = s + ri * p; col = ci * p;     }
    else             { row = ri * p;     col = s + ci * p; }
    return (row << 6) + col;
}
__device__ __forceinline__ int grp_start(int j) {
    if (j == 0) return 0;
    int m = (31 - __clz((unsigned)j)) >> 1;
    return (j >> (2 * m)) << (2 * m);
}
__device__ __forceinline__ int grp_end(int j) {
    if (j == 0) return 1;
    int m = (31 - __clz((unsigned)j)) >> 1;
    return ((j >> (2 * m)) + 1) << (2 * m);
}

// ---------------- small PTX helpers -------------------------------------------
__device__ __forceinline__ uint32_t smem_u32(const void* p) {
    uint32_t a;
    asm("{ .reg .u64 t; cvta.to.shared.u64 t, %1; cvt.u32.u64 %0, t; }" : "=r"(a) : "l"(p));
    return a;
}
#define SWZ(o) ((o) ^ (((o) >> 3) & 0x70))

__device__ __forceinline__ void cp_async16(uint32_t dst, const void* src) {
    asm volatile("cp.async.cg.shared.global [%0], [%1], 16;" :: "r"(dst), "l"(src) : "memory");
}
__device__ __forceinline__ void cp_commit() {
    asm volatile("cp.async.commit_group;" ::: "memory");
}
template<int N>
__device__ __forceinline__ void cp_wait() {
    asm volatile("cp.async.wait_group %0;" :: "n"(N) : "memory");
}
__device__ __forceinline__ void ldm_x4(uint32_t addr, uint32_t& r0, uint32_t& r1,
                                       uint32_t& r2, uint32_t& r3) {
    asm volatile("ldmatrix.sync.aligned.m8n8.x4.shared.b16 {%0,%1,%2,%3}, [%4];"
                 : "=r"(r0), "=r"(r1), "=r"(r2), "=r"(r3) : "r"(addr));
}
__device__ __forceinline__ void mma16816(float* c, uint32_t a0, uint32_t a1, uint32_t a2,
                                         uint32_t a3, uint32_t b0, uint32_t b1) {
    asm volatile("mma.sync.aligned.m16n8k16.row.col.f32.f16.f16.f32 "
                 "{%0,%1,%2,%3},{%4,%5,%6,%7},{%8,%9},{%0,%1,%2,%3};"
                 : "+f"(c[0]), "+f"(c[1]), "+f"(c[2]), "+f"(c[3])
                 : "r"(a0), "r"(a1), "r"(a2), "r"(a3), "r"(b0), "r"(b1));
}

// ---------------- gather: fold input to fp16 ----------------------------------
__global__ void gather_kernel(const float* __restrict__ x) {
    int idx = blockIdx.x * blockDim.x + threadIdx.x;   // 128*4096
    int j = idx & (NFEAT - 1);
    int b = idx >> 12;
    ((half*)g_xh_raw)[idx] = __float2half_rn(x[(b << 12) + perm_site(j)]);
}

// ---------------- masked GEMM via mma.sync, 3-deep cp.async pipeline -----------
// D[m, r0+n] = sum_c X[m,c] * W[r0+n,c]   (per-row contiguous cutoff mask)
// M=128 (batch), N-tile=32, K-stage=64. 256 thr / 8 warps, warp = m16 x n32.
// A: fp16 cp.async ring (3 x 16KB, SW128-swizzled, ldmatrix).
// W: fp32 cp.async ring (3 x 8.5KB, row pad 68 floats); B fragments built
//    directly from fp32 SMEM (LDS.64 + mask-select + cvt), no STS/ldmatrix.
#define OFF_A 1024
#define OFF_W (1024 + 3 * 16384)
#define W_STRIDE 272                       /* 68 floats per n-row */
#define SMEM_TOTAL (OFF_W + 3 * 8704)

template<int HALVES, bool EXCL, int EPI, int SEL>
__global__ __launch_bounds__(256, 2)
void mma_kernel(const float* __restrict__ W,
                const float* __restrict__ bias,
                const float* __restrict__ alpha,
                float* __restrict__ outp)
{
    extern __shared__ __align__(1024) char smem[];
    const uint32_t smem_base = smem_u32(smem);
    const int t = threadIdx.x;
    const int wid = t >> 5, lane = t & 31;
    const int C = (SEL == 0) ? NFEAT : 2 * NFEAT;
    const half* Asrc = (SEL == 0) ? (const half*)g_xh_raw
                     : (SEL == 1) ? (const half*)g_act0_raw
                                  : (const half*)g_act1_raw;
    half* actout = (SEL == 0) ? (half*)g_act0_raw : (half*)g_act1_raw;

    // long-K-first block ordering (cutoffs monotone in row index)
    int r0;
    if (EPI == 1) {
        r0 = ((int)gridDim.x - 1 - (int)blockIdx.x) * 32;
    } else {
        int rowblock = ((int)gridDim.x >> 1) - 1 - ((int)blockIdx.x >> 1);
        r0 = (blockIdx.x & 1) * NFEAT + rowblock * 32;
    }

    int* cut_s = (int*)smem;
    if (t < 32) {
        int rmod = (r0 + t) & (NFEAT - 1);
        cut_s[t] = EXCL ? grp_start(rmod) : grp_end(rmod);
    }
    __syncthreads();

    const int Kmax = cut_s[31];               // cutoffs monotone within tile
    const int nk = (Kmax + 63) >> 6;          // K-stages per 4096-half
    const int S = HALVES * nk;

    // W producer lane mapping: n-row + two 16B chunks per thread
    const int wn = t >> 3;                    // 0..31
    const int wc = t & 7;                     // chunk base 0..7 (also +8)
    const int wcut = cut_s[wn];
    // consumer per-lane cutoffs for its 4 n positions
    int cutn[4];
#pragma unroll
    for (int ni = 0; ni < 4; ni++) cutn[ni] = cut_s[ni * 8 + (lane >> 2)];

    auto produce = [&](int s) {
        if (s < S) {
            const int hh = (HALVES == 2 && s >= nk) ? 1 : 0;
            const int kks = s - hh * nk;
            const int buf = s % 3;
            // A tile 128x64 fp16
            const half* Ah = Asrc + hh * NFEAT + (kks << 6);
            uint32_t Ab = smem_base + OFF_A + buf * 16384;
#pragma unroll
            for (int l = 0; l < 4; l++) {
                int fid = t + l * 256;
                int m = fid >> 3, c16 = fid & 7;
                cp_async16(Ab + SWZ(m * 128 + c16 * 16), Ah + (size_t)m * C + c16 * 8);
            }
            // W tile 32x64 fp32 (masked chunk skip)
            uint32_t Wb = smem_base + OFF_W + buf * 8704;
            const float* Wrow = W + (size_t)(r0 + wn) * C + hh * NFEAT + (kks << 6);
            const int klo = kks << 6;
#pragma unroll
            for (int l = 0; l < 2; l++) {
                int cc = wc + l * 8;
                if (klo + cc * 4 < wcut)
                    cp_async16(Wb + wn * W_STRIDE + cc * 16, Wrow + cc * 4);
            }
        }
        cp_commit();   // always commit (dummy groups keep wait-count invariant)
    };

    float acc[4][4];
#pragma unroll
    for (int i = 0; i < 4; i++)
#pragma unroll
        for (int j = 0; j < 4; j++) acc[i][j] = 0.f;

    const int rowA = wid * 16 + (lane & 15);
    const int colHi = (lane >> 4) * 8;
    const int nlane = lane >> 2;      // n within 8-group
    const int klane = (lane & 3) * 2; // k pair within 8

    produce(0);
    produce(1);

    for (int s = 0; s < S; s++) {
        cp_wait<1>();
        __syncthreads();
        produce(s + 2);

        const int buf = s % 3;
        const int hh = (HALVES == 2 && s >= nk) ? 1 : 0;
        const int kbase = (s - hh * nk) << 6;     // local k within 4096-half
        const uint32_t Ab = smem_base + OFF_A + buf * 16384;
        const float* Wf = (const float*)(smem + OFF_W + buf * 8704);

#pragma unroll
        for (int kk = 0; kk < 4; kk++) {
            uint32_t a0, a1, a2, a3;
            const int kc = kk * 16 + colHi;
            ldm_x4(Ab + SWZ(rowA * 128 + kc * 2), a0, a1, a2, a3);
            const int kof = kk * 16 + klane;
            const int ke = kbase + kof;
#pragma unroll
            for (int ni = 0; ni < 4; ni++) {
                const int n = ni * 8 + nlane;
                const float* p = Wf + n * 68 + kof;
                float2 v0 = *(const float2*)(p);
                float2 v1 = *(const float2*)(p + 8);
                const int cut = cutn[ni];
                float x0 = (ke     < cut) ? v0.x : 0.f;
                float y0 = (ke + 1 < cut) ? v0.y : 0.f;
                float x1 = (ke + 8 < cut) ? v1.x : 0.f;
                float y1 = (ke + 9 < cut) ? v1.y : 0.f;
                half2 b0 = __floats2half2_rn(x0, y0);
                half2 b1 = __floats2half2_rn(x1, y1);
                mma16816(acc[ni], a0, a1, a2, a3,
                         *(uint32_t*)&b0, *(uint32_t*)&b1);
            }
        }
    }

    // ---- fused epilogue (registers -> global)
    const int m = wid * 16 + (lane >> 2);      // rows m and m+8
#pragma unroll
    for (int ni = 0; ni < 4; ni++) {
        int r = r0 + ni * 8 + klane;
        if (EPI == 0) {
            float bx = __ldg(bias + r), by = __ldg(bias + r + 1);
            float ax = __ldg(alpha + r), ay = __ldg(alpha + r + 1);
            float v0 = acc[ni][0] + bx, v1 = acc[ni][1] + by;
            float v2 = acc[ni][2] + bx, v3 = acc[ni][3] + by;
            v0 = (v0 > 0.f) ? v0 : ax * v0;
            v1 = (v1 > 0.f) ? v1 : ay * v1;
            v2 = (v2 > 0.f) ? v2 : ax * v2;
            v3 = (v3 > 0.f) ? v3 : ay * v3;
            *(half2*)(actout + (size_t)m * (2 * NFEAT) + r) = __floats2half2_rn(v0, v1);
            *(half2*)(actout + (size_t)(m + 8) * (2 * NFEAT) + r) = __floats2half2_rn(v2, v3);
        } else {
            float bx = __ldg(bias + r), by = __ldg(bias + r + 1);
            int s0 = perm_site(r), s1 = perm_site(r + 1);
            float v0 = acc[ni][0] + bx, v1 = acc[ni][1] + by;
            float v2 = acc[ni][2] + bx, v3 = acc[ni][3] + by;
            float g0 = (r == 0) ? 0.5f : 1.f / (1.f + __expf(-v0));
            float g2 = (r == 0) ? 0.5f : 1.f / (1.f + __expf(-v2));
            float g1 = 1.f / (1.f + __expf(-v1));
            float g3 = 1.f / (1.f + __expf(-v3));
            outp[(size_t)m * NFEAT + s0] = g0;
            outp[(size_t)m * NFEAT + s1] = g1;
            outp[(size_t)(m + 8) * NFEAT + s0] = g2;
            outp[(size_t)(m + 8) * NFEAT + s1] = g3;
        }
    }
}

// ---------------- launcher ------------------------------------------------------
extern "C" void kernel_launch(void* const* d_in, const int* in_sizes, int n_in,
                              void* d_out, int out_size) {
    const float* x  = (const float*)d_in[0];
    const float* W0 = (const float*)d_in[1];
    const float* b0 = (const float*)d_in[2];
    const float* a1 = (const float*)d_in[3];
    const float* W1 = (const float*)d_in[4];
    const float* b1 = (const float*)d_in[5];
    const float* a2 = (const float*)d_in[6];
    const float* W2 = (const float*)d_in[7];
    const float* b2 = (const float*)d_in[8];
    float* out = (float*)d_out;

    cudaFuncSetAttribute(mma_kernel<1, true,  0, 0>, cudaFuncAttributeMaxDynamicSharedMemorySize, SMEM_TOTAL);
    cudaFuncSetAttribute(mma_kernel<2, false, 0, 1>, cudaFuncAttributeMaxDynamicSharedMemorySize, SMEM_TOTAL);
    cudaFuncSetAttribute(mma_kernel<2, false, 1, 2>, cudaFuncAttributeMaxDynamicSharedMemorySize, SMEM_TOTAL);

    gather_kernel<<<(BATCH * NFEAT) / 256, 256>>>(x);

    // L0: exclusive mask, C=4096, PReLU(a1) -> g_act0 [128, 8192]
    mma_kernel<1, true,  0, 0><<<256, 256, SMEM_TOTAL>>>(W0, b0, a1, nullptr);
    // L1: inclusive mask, C=8192, PReLU(a2) -> g_act1 [128, 8192]
    mma_kernel<2, false, 0, 1><<<256, 256, SMEM_TOTAL>>>(W1, b1, a2, nullptr);
    // L2: inclusive mask, C=8192, sigmoid + xhat mask/bias + unfold scatter
    mma_kernel<2, false, 1, 2><<<128, 256, SMEM_TOTAL>>>(W2, b2, nullptr, out);
}

// round 5
// speedup vs baseline: 15.7056x; 1.7050x over previous
#include <cuda_runtime.h>
#include <cuda_fp16.h>
#include <math.h>
#include <stdint.h>

#define NFEAT 4096
#define BATCH 128

// ---------------- device scratch (static; no runtime allocation) -------------
__device__ float4 g_xh_raw[BATCH * NFEAT / 8];        // half [128, 4096] folded x
__device__ float4 g_act0_raw[BATCH * 2 * NFEAT / 8];  // half [128, 8192] layer0 out
__device__ float4 g_act1_raw[BATCH * 2 * NFEAT / 8];  // half [128, 8192] layer1 out
__device__ float  g_l2part[2 * BATCH * NFEAT];        // split-K partials for L2

// ---------------- closed-form fold / mask helpers ----------------------------
__device__ __forceinline__ int perm_site(int j) {
    if (j == 0) return 0;
    int m = (31 - __clz((unsigned)j)) >> 1;   // floor(log4 j)
    int q = j >> (2 * m);
    int t = j - (q << (2 * m));
    int ri = t >> m;
    int ci = t & ((1 << m) - 1);
    int s = 1 << (5 - m);
    int p = s << 1;
    int row, col;
    if (q == 1)      { row = s + ri * p; col = s + ci * p; }
    else if (q == 2) { row = s + ri * p; col = ci * p;     }
    else             { row = ri * p;     col = s + ci * p; }
    return (row << 6) + col;
}
__device__ __forceinline__ int grp_start(int j) {
    if (j == 0) return 0;
    int m = (31 - __clz((unsigned)j)) >> 1;
    return (j >> (2 * m)) << (2 * m);
}
__device__ __forceinline__ int grp_end(int j) {
    if (j == 0) return 1;
    int m = (31 - __clz((unsigned)j)) >> 1;
    return ((j >> (2 * m)) + 1) << (2 * m);
}

// ---------------- small PTX helpers -------------------------------------------
__device__ __forceinline__ uint32_t smem_u32(const void* p) {
    uint32_t a;
    asm("{ .reg .u64 t; cvta.to.shared.u64 t, %1; cvt.u32.u64 %0, t; }" : "=r"(a) : "l"(p));
    return a;
}
#define SWZ(o) ((o) ^ (((o) >> 3) & 0x70))

__device__ __forceinline__ void cp_async16(uint32_t dst, const void* src) {
    asm volatile("cp.async.cg.shared.global [%0], [%1], 16;" :: "r"(dst), "l"(src) : "memory");
}
__device__ __forceinline__ void cp_commit() {
    asm volatile("cp.async.commit_group;" ::: "memory");
}
template<int N>
__device__ __forceinline__ void cp_wait() {
    asm volatile("cp.async.wait_group %0;" :: "n"(N) : "memory");
}
__device__ __forceinline__ void ldm_x4(uint32_t addr, uint32_t& r0, uint32_t& r1,
                                       uint32_t& r2, uint32_t& r3) {
    asm volatile("ldmatrix.sync.aligned.m8n8.x4.shared.b16 {%0,%1,%2,%3}, [%4];"
                 : "=r"(r0), "=r"(r1), "=r"(r2), "=r"(r3) : "r"(addr));
}
__device__ __forceinline__ void mma16816(float* c, uint32_t a0, uint32_t a1, uint32_t a2,
                                         uint32_t a3, uint32_t b0, uint32_t b1) {
    asm volatile("mma.sync.aligned.m16n8k16.row.col.f32.f16.f16.f32 "
                 "{%0,%1,%2,%3},{%4,%5,%6,%7},{%8,%9},{%0,%1,%2,%3};"
                 : "+f"(c[0]), "+f"(c[1]), "+f"(c[2]), "+f"(c[3])
                 : "r"(a0), "r"(a1), "r"(a2), "r"(a3), "r"(b0), "r"(b1));
}

// ---------------- gather: fold input to fp16 ----------------------------------
__global__ void gather_kernel(const float* __restrict__ x) {
    int idx = blockIdx.x * blockDim.x + threadIdx.x;   // 128*4096
    int j = idx & (NFEAT - 1);
    int b = idx >> 12;
    ((half*)g_xh_raw)[idx] = __float2half_rn(x[(b << 12) + perm_site(j)]);
}

// ---------------- masked GEMM: cp.async ring + coop fp16 convert + mma.sync ----
// D[m, r0+n] = sum_c X[m,c] * W[r0+n,c]   (per-row contiguous cutoff mask)
// M=128 (batch), N-tile=32, K-stage=64. 256 thr / 8 warps, warp = m16 x n32.
// A: fp16 cp.async ring (3 x 16KB, SW128, ldmatrix).
// W: fp32 cp.async ring (3 x 8.5KB, padded rows) -> per-stage cooperative
//    mask+convert into one 4KB SW128 fp16 tile -> ldmatrix B.
#define OFF_A 1024
#define OFF_W (OFF_A + 3 * 16384)
#define OFF_H (OFF_W + 3 * 8704)
#define W_STRIDE 272                       /* 68 floats per n-row */
#define SMEM_TOTAL (OFF_H + 4096)

template<int HALVES, bool EXCL, int EPI, int SEL>
__global__ __launch_bounds__(256, 2)
void mma_kernel(const float* __restrict__ W,
                const float* __restrict__ bias,
                const float* __restrict__ alpha,
                float* __restrict__ outp)
{
    extern __shared__ __align__(1024) char smem[];
    const uint32_t smem_base = smem_u32(smem);
    const int t = threadIdx.x;
    const int wid = t >> 5, lane = t & 31;
    const int C = (SEL == 0) ? NFEAT : 2 * NFEAT;
    const half* Asrc = (SEL == 0) ? (const half*)g_xh_raw
                     : (SEL == 1) ? (const half*)g_act0_raw
                                  : (const half*)g_act1_raw;
    half* actout = (SEL == 0) ? (half*)g_act0_raw : (half*)g_act1_raw;

    // block -> (r0, hoff): long-K-first (cutoffs monotone in row index)
    int r0, hoff, ks = 0;
    if (EPI == 1) {
        ks = blockIdx.x & 1;                          // split-K half
        int rb = ((int)gridDim.x >> 1) - 1 - ((int)blockIdx.x >> 1);
        r0 = rb * 32;
        hoff = ks * NFEAT;
    } else {
        int rb = ((int)gridDim.x >> 1) - 1 - ((int)blockIdx.x >> 1);
        r0 = (blockIdx.x & 1) * NFEAT + rb * 32;
        hoff = 0;
    }

    int* cut_s = (int*)smem;
    if (t < 32) {
        int rmod = (r0 + t) & (NFEAT - 1);
        cut_s[t] = EXCL ? grp_start(rmod) : grp_end(rmod);
    }
    __syncthreads();

    const int Kmax = cut_s[31];               // cutoffs monotone within tile
    const int nk = (Kmax + 63) >> 6;          // K-stages per 4096-half
    const int S = HALVES * nk;

    // producer lane mapping for W: n-row + two 16B chunks per thread
    const int wn = t >> 3;                    // 0..31
    const int wc = t & 7;                     // chunk base (also +8)
    const int wcut = cut_s[wn];
    // convert-pass lane mapping: same n-row, 8-element k chunk
    const int cvcut = wcut;

    auto produce = [&](int s) {
        if (s < S) {
            const int hh = (HALVES == 2 && s >= nk) ? 1 : 0;
            const int kks = s - hh * nk;
            const int buf = s % 3;
            // A tile 128 x 64 fp16
            const half* Ah = Asrc + hoff + hh * NFEAT + (kks << 6);
            uint32_t Ab = smem_base + OFF_A + buf * 16384;
#pragma unroll
            for (int l = 0; l < 4; l++) {
                int fid = t + l * 256;
                int m = fid >> 3, c16 = fid & 7;
                cp_async16(Ab + SWZ(m * 128 + c16 * 16), Ah + (size_t)m * C + c16 * 8);
            }
            // W tile 32 x 64 fp32 (masked chunk skip)
            uint32_t Wb = smem_base + OFF_W + buf * 8704;
            const float* Wrow = W + (size_t)(r0 + wn) * C + hoff + hh * NFEAT + (kks << 6);
            const int klo = kks << 6;
#pragma unroll
            for (int l = 0; l < 2; l++) {
                int cc = wc + l * 8;
                if (klo + cc * 4 < wcut)
                    cp_async16(Wb + wn * W_STRIDE + cc * 16, Wrow + cc * 4);
            }
        }
        cp_commit();   // always commit (dummy groups keep wait-count invariant)
    };

    float acc[4][4];
#pragma unroll
    for (int i = 0; i < 4; i++)
#pragma unroll
        for (int j = 0; j < 4; j++) acc[i][j] = 0.f;

    const int rowA = wid * 16 + (lane & 15);
    const int rowB = lane & 15;
    const int colHi = (lane >> 4) * 8;
    const int klane = (lane & 3) * 2;

    produce(0);
    produce(1);

    for (int s = 0; s < S; s++) {
        cp_wait<1>();
        __syncthreads();

        const int buf = s % 3;
        const int hh = (HALVES == 2 && s >= nk) ? 1 : 0;
        const int kbase = (s - hh * nk) << 6;      // local k within 4096-half

        // ---- cooperative mask + fp32->fp16 convert (each element once)
        {
            const float* Wf = (const float*)(smem + OFF_W + buf * 8704);
            const float* p = Wf + wn * 68 + wc * 8;
            float4 u0 = *(const float4*)(p);
            float4 u1 = *(const float4*)(p + 4);
            const int ke = kbase + wc * 8;
            half2 h0 = __floats2half2_rn((ke     < cvcut) ? u0.x : 0.f,
                                         (ke + 1 < cvcut) ? u0.y : 0.f);
            half2 h1 = __floats2half2_rn((ke + 2 < cvcut) ? u0.z : 0.f,
                                         (ke + 3 < cvcut) ? u0.w : 0.f);
            half2 h2 = __floats2half2_rn((ke + 4 < cvcut) ? u1.x : 0.f,
                                         (ke + 5 < cvcut) ? u1.y : 0.f);
            half2 h3 = __floats2half2_rn((ke + 6 < cvcut) ? u1.z : 0.f,
                                         (ke + 7 < cvcut) ? u1.w : 0.f);
            uint4 pk;
            pk.x = *(uint32_t*)&h0; pk.y = *(uint32_t*)&h1;
            pk.z = *(uint32_t*)&h2; pk.w = *(uint32_t*)&h3;
            *(uint4*)(smem + OFF_H + SWZ(wn * 128 + wc * 16)) = pk;
        }
        __syncthreads();
        produce(s + 2);

        const uint32_t Ab = smem_base + OFF_A + buf * 16384;
        const uint32_t Hb = smem_base + OFF_H;
#pragma unroll
        for (int kk = 0; kk < 4; kk++) {
            const int kc = kk * 16 + colHi;
            uint32_t a0, a1, a2, a3, p0, p1, p2, p3, q0, q1, q2, q3;
            ldm_x4(Ab + SWZ(rowA * 128 + kc * 2), a0, a1, a2, a3);
            ldm_x4(Hb + SWZ(rowB * 128 + kc * 2), p0, p1, p2, p3);
            ldm_x4(Hb + SWZ((rowB + 16) * 128 + kc * 2), q0, q1, q2, q3);
            mma16816(acc[0], a0, a1, a2, a3, p0, p2);
            mma16816(acc[1], a0, a1, a2, a3, p1, p3);
            mma16816(acc[2], a0, a1, a2, a3, q0, q2);
            mma16816(acc[3], a0, a1, a2, a3, q1, q3);
        }
    }

    // ---- epilogue
    const int m = wid * 16 + (lane >> 2);      // rows m and m+8
#pragma unroll
    for (int ni = 0; ni < 4; ni++) {
        int r = r0 + ni * 8 + klane;
        if (EPI == 0) {
            float bx = __ldg(bias + r), by = __ldg(bias + r + 1);
            float ax = __ldg(alpha + r), ay = __ldg(alpha + r + 1);
            float v0 = acc[ni][0] + bx, v1 = acc[ni][1] + by;
            float v2 = acc[ni][2] + bx, v3 = acc[ni][3] + by;
            v0 = (v0 > 0.f) ? v0 : ax * v0;
            v1 = (v1 > 0.f) ? v1 : ay * v1;
            v2 = (v2 > 0.f) ? v2 : ax * v2;
            v3 = (v3 > 0.f) ? v3 : ay * v3;
            *(half2*)(actout + (size_t)m * (2 * NFEAT) + r) = __floats2half2_rn(v0, v1);
            *(half2*)(actout + (size_t)(m + 8) * (2 * NFEAT) + r) = __floats2half2_rn(v2, v3);
        } else {
            // split-K partial store (no bias/activation here)
            float* part = g_l2part + (size_t)ks * (BATCH * NFEAT);
            *(float2*)(part + (size_t)m * NFEAT + r) = make_float2(acc[ni][0], acc[ni][1]);
            *(float2*)(part + (size_t)(m + 8) * NFEAT + r) = make_float2(acc[ni][2], acc[ni][3]);
        }
    }
}

// ---------------- L2 final: add partials + bias, sigmoid, unfold scatter -------
__global__ void l2_final_kernel(const float* __restrict__ bias, float* __restrict__ out) {
    int idx = blockIdx.x * blockDim.x + threadIdx.x;   // 128*4096
    int r = idx & (NFEAT - 1);
    int m = idx >> 12;
    float v = g_l2part[idx] + g_l2part[idx + BATCH * NFEAT] + __ldg(bias + r);
    float g = (r == 0) ? 0.5f : 1.f / (1.f + __expf(-v));
    out[(m << 12) + perm_site(r)] = g;
}

// ---------------- launcher ------------------------------------------------------
extern "C" void kernel_launch(void* const* d_in, const int* in_sizes, int n_in,
                              void* d_out, int out_size) {
    const float* x  = (const float*)d_in[0];
    const float* W0 = (const float*)d_in[1];
    const float* b0 = (const float*)d_in[2];
    const float* a1 = (const float*)d_in[3];
    const float* W1 = (const float*)d_in[4];
    const float* b1 = (const float*)d_in[5];
    const float* a2 = (const float*)d_in[6];
    const float* W2 = (const float*)d_in[7];
    const float* b2 = (const float*)d_in[8];
    float* out = (float*)d_out;

    cudaFuncSetAttribute(mma_kernel<1, true,  0, 0>, cudaFuncAttributeMaxDynamicSharedMemorySize, SMEM_TOTAL);
    cudaFuncSetAttribute(mma_kernel<2, false, 0, 1>, cudaFuncAttributeMaxDynamicSharedMemorySize, SMEM_TOTAL);
    cudaFuncSetAttribute(mma_kernel<1, false, 1, 2>, cudaFuncAttributeMaxDynamicSharedMemorySize, SMEM_TOTAL);

    gather_kernel<<<(BATCH * NFEAT) / 256, 256>>>(x);

    // L0: exclusive mask, C=4096, PReLU(a1) -> g_act0 [128, 8192]
    mma_kernel<1, true,  0, 0><<<256, 256, SMEM_TOTAL>>>(W0, b0, a1, nullptr);
    // L1: inclusive mask, C=8192, PReLU(a2) -> g_act1 [128, 8192]
    mma_kernel<2, false, 0, 1><<<256, 256, SMEM_TOTAL>>>(W1, b1, a2, nullptr);
    // L2: inclusive mask, split-K over the two 4096-halves -> fp32 partials
    mma_kernel<1, false, 1, 2><<<256, 256, SMEM_TOTAL>>>(W2, b2, nullptr, nullptr);
    // L2 reduce: add halves + bias, sigmoid, xhat mask/bias, unfold scatter
    l2_final_kernel<<<(BATCH * NFEAT) / 256, 256>>>(b2, out);
}

// round 7
// speedup vs baseline: 17.2764x; 1.1000x over previous
#include <cuda_runtime.h>
#include <cuda_fp16.h>
#include <math.h>
#include <stdint.h>

#define NFEAT 4096
#define BATCH 128

// ---------------- device scratch (static; no runtime allocation) -------------
__device__ float4 g_xh_raw[BATCH * NFEAT / 8];        // half [128, 4096] folded x
__device__ float4 g_act0_raw[BATCH * 2 * NFEAT / 8];  // half [128, 8192] layer0 out
__device__ float4 g_act1_raw[BATCH * 2 * NFEAT / 8];  // half [128, 8192] layer1 out
__device__ float  g_part[4 * BATCH * 2 * NFEAT];      // split-K fp32 partials (16MB)

// ---------------- closed-form fold / mask helpers ----------------------------
__device__ __forceinline__ int perm_site(int j) {
    if (j == 0) return 0;
    int m = (31 - __clz((unsigned)j)) >> 1;   // floor(log4 j)
    int q = j >> (2 * m);
    int t = j - (q << (2 * m));
    int ri = t >> m;
    int ci = t & ((1 << m) - 1);
    int s = 1 << (5 - m);
    int p = s << 1;
    int row, col;
    if (q == 1)      { row = s + ri * p; col = s + ci * p; }
    else if (q == 2) { row = s + ri * p; col = ci * p;     }
    else             { row = ri * p;     col = s + ci * p; }
    return (row << 6) + col;
}
__device__ __forceinline__ int grp_start(int j) {
    if (j == 0) return 0;
    int m = (31 - __clz((unsigned)j)) >> 1;
    return (j >> (2 * m)) << (2 * m);
}
__device__ __forceinline__ int grp_end(int j) {
    if (j == 0) return 1;
    int m = (31 - __clz((unsigned)j)) >> 1;
    return ((j >> (2 * m)) + 1) << (2 * m);
}

// ---------------- small PTX helpers -------------------------------------------
__device__ __forceinline__ uint32_t smem_u32(const void* p) {
    uint32_t a;
    asm("{ .reg .u64 t; cvta.to.shared.u64 t, %1; cvt.u32.u64 %0, t; }" : "=r"(a) : "l"(p));
    return a;
}
#define SWZ(o) ((o) ^ (((o) >> 3) & 0x70))

__device__ __forceinline__ void cp_async16(uint32_t dst, const void* src) {
    asm volatile("cp.async.cg.shared.global [%0], [%1], 16;" :: "r"(dst), "l"(src) : "memory");
}
__device__ __forceinline__ void cp_commit() {
    asm volatile("cp.async.commit_group;" ::: "memory");
}
template<int N>
__device__ __forceinline__ void cp_wait() {
    asm volatile("cp.async.wait_group %0;" :: "n"(N) : "memory");
}
__device__ __forceinline__ void ldm_x4(uint32_t addr, uint32_t& r0, uint32_t& r1,
                                       uint32_t& r2, uint32_t& r3) {
    asm volatile("ldmatrix.sync.aligned.m8n8.x4.shared.b16 {%0,%1,%2,%3}, [%4];"
                 : "=r"(r0), "=r"(r1), "=r"(r2), "=r"(r3) : "r"(addr));
}
__device__ __forceinline__ void mma16816(float* c, uint32_t a0, uint32_t a1, uint32_t a2,
                                         uint32_t a3, uint32_t b0, uint32_t b1) {
    asm volatile("mma.sync.aligned.m16n8k16.row.col.f32.f16.f16.f32 "
                 "{%0,%1,%2,%3},{%4,%5,%6,%7},{%8,%9},{%0,%1,%2,%3};"
                 : "+f"(c[0]), "+f"(c[1]), "+f"(c[2]), "+f"(c[3])
                 : "r"(a0), "r"(a1), "r"(a2), "r"(a3), "r"(b0), "r"(b1));
}

// ---------------- gather: fold input to fp16 ----------------------------------
__global__ void gather_kernel(const float* __restrict__ x) {
    int idx = blockIdx.x * blockDim.x + threadIdx.x;   // 128*4096
    int j = idx & (NFEAT - 1);
    int b = idx >> 12;
    ((half*)g_xh_raw)[idx] = __float2half_rn(x[(b << 12) + perm_site(j)]);
}

// ---------------- masked GEMM: split-K partials via mma.sync --------------------
// Partial[p][m][r] = sum_{c in this CTA's K-slice, c < cut(r)} X[m,c] * W[r,c]
// M=128 (batch), N-tile=32, K-stage=64, K-slice=2048 (<=32 stages per CTA).
// A: fp16 cp.async ring (3 x 16KB, SW128, ldmatrix).
// W: fp32 cp.async ring (2 x 8.5KB) -> coop mask+cvt -> 4KB fp16 tile -> ldmatrix.
#define OFF_A 1024
#define OFF_W (OFF_A + 3 * 16384)
#define OFF_H (OFF_W + 2 * 8704)
#define W_STRIDE 272                       /* 68 floats per n-row */
#define SMEM_TOTAL (OFF_H + 4096)

template<int HALVES, int SP, bool EXCL, int SEL>
__global__ __launch_bounds__(256, 3)
void mma_kernel(const float* __restrict__ W)
{
    extern __shared__ __align__(1024) char smem[];
    const uint32_t smem_base = smem_u32(smem);
    const int t = threadIdx.x;
    const int wid = t >> 5, lane = t & 31;
    const int RB = (SEL == 2) ? 128 : 256;          // 32-row blocks
    const int R  = RB * 32;
    const int C  = (SEL == 0) ? NFEAT : 2 * NFEAT;  // input features
    const int NPART = HALVES * SP;
    const int KS = NFEAT / SP;                      // K-slice within a half
    const half* Asrc = (SEL == 0) ? (const half*)g_xh_raw
                     : (SEL == 1) ? (const half*)g_act0_raw
                                  : (const half*)g_act1_raw;

    // block decode: sibling parts adjacent; long-K rowblocks first
    const int ks  = (int)blockIdx.x % NPART;
    const int rb  = RB - 1 - ((int)blockIdx.x / NPART);
    const int r0  = rb * 32;
    const int hsel = ks % HALVES;
    const int sub  = ks / HALVES;
    const int hoff = hsel * NFEAT;
    const int kst  = sub * KS;

    int* cut_s = (int*)smem;
    if (t < 32) {
        int rmod = (r0 + t) & (NFEAT - 1);
        cut_s[t] = EXCL ? grp_start(rmod) : grp_end(rmod);
    }
    __syncthreads();

    const int Kmax = cut_s[31];               // cutoffs monotone within tile
    const int span = (Kmax - kst < KS) ? (Kmax - kst) : KS;
    const int S = (span > 0) ? ((span + 63) >> 6) : 0;

    // producer lane mapping for W: n-row + two 16B chunks per thread
    const int wn = t >> 3;                    // 0..31
    const int wc = t & 7;                     // chunk base (also +8)
    const int wcut = cut_s[wn];

    auto produce = [&](int s) {
        if (s < S) {
            const int k0 = kst + (s << 6);
            const int buf = s % 3;
            // A tile 128 x 64 fp16
            const half* Ah = Asrc + hoff + k0;
            uint32_t Ab = smem_base + OFF_A + buf * 16384;
#pragma unroll
            for (int l = 0; l < 4; l++) {
                int fid = t + l * 256;
                int m = fid >> 3, c16 = fid & 7;
                cp_async16(Ab + SWZ(m * 128 + c16 * 16), Ah + (size_t)m * C + c16 * 8);
            }
            // W tile 32 x 64 fp32 (masked chunk skip), 2-deep ring
            uint32_t Wb = smem_base + OFF_W + (s & 1) * 8704;
            const float* Wrow = W + (size_t)(r0 + wn) * C + hoff + k0;
#pragma unroll
            for (int l = 0; l < 2; l++) {
                int cc = wc + l * 8;
                if (k0 + cc * 4 < wcut)
                    cp_async16(Wb + wn * W_STRIDE + cc * 16, Wrow + cc * 4);
            }
        }
        cp_commit();   // always commit (dummy groups keep wait-count invariant)
    };

    float acc[4][4];
#pragma unroll
    for (int i = 0; i < 4; i++)
#pragma unroll
        for (int j = 0; j < 4; j++) acc[i][j] = 0.f;

    const int rowA = wid * 16 + (lane & 15);
    const int rowB = lane & 15;
    const int colHi = (lane >> 4) * 8;
    const int klane = (lane & 3) * 2;

    produce(0);
    produce(1);

    for (int s = 0; s < S; s++) {
        cp_wait<1>();
        __syncthreads();

        const int buf = s % 3;
        const int k0 = kst + (s << 6);

        // ---- cooperative mask + fp32->fp16 convert (each element once)
        {
            const float* Wf = (const float*)(smem + OFF_W + (s & 1) * 8704);
            const float* p = Wf + wn * 68 + wc * 8;
            float4 u0 = *(const float4*)(p);
            float4 u1 = *(const float4*)(p + 4);
            const int ke = k0 + wc * 8;
            half2 h0 = __floats2half2_rn((ke     < wcut) ? u0.x : 0.f,
                                         (ke + 1 < wcut) ? u0.y : 0.f);
            half2 h1 = __floats2half2_rn((ke + 2 < wcut) ? u0.z : 0.f,
                                         (ke + 3 < wcut) ? u0.w : 0.f);
            half2 h2 = __floats2half2_rn((ke + 4 < wcut) ? u1.x : 0.f,
                                         (ke + 5 < wcut) ? u1.y : 0.f);
            half2 h3 = __floats2half2_rn((ke + 6 < wcut) ? u1.z : 0.f,
                                         (ke + 7 < wcut) ? u1.w : 0.f);
            uint4 pk;
            pk.x = *(uint32_t*)&h0; pk.y = *(uint32_t*)&h1;
            pk.z = *(uint32_t*)&h2; pk.w = *(uint32_t*)&h3;
            *(uint4*)(smem + OFF_H + SWZ(wn * 128 + wc * 16)) = pk;
        }
        __syncthreads();
        produce(s + 2);

        const uint32_t Ab = smem_base + OFF_A + buf * 16384;
        const uint32_t Hb = smem_base + OFF_H;
#pragma unroll
        for (int kk = 0; kk < 4; kk++) {
            const int kc = kk * 16 + colHi;
            uint32_t a0, a1, a2, a3, p0, p1, p2, p3, q0, q1, q2, q3;
            ldm_x4(Ab + SWZ(rowA * 128 + kc * 2), a0, a1, a2, a3);
            ldm_x4(Hb + SWZ(rowB * 128 + kc * 2), p0, p1, p2, p3);
            ldm_x4(Hb + SWZ((rowB + 16) * 128 + kc * 2), q0, q1, q2, q3);
            mma16816(acc[0], a0, a1, a2, a3, p0, p2);
            mma16816(acc[1], a0, a1, a2, a3, p1, p3);
            mma16816(acc[2], a0, a1, a2, a3, q0, q2);
            mma16816(acc[3], a0, a1, a2, a3, q1, q3);
        }
    }

    // ---- epilogue: fp32 partial store
    float* part = g_part + (size_t)ks * (BATCH * 2 * NFEAT);
    const int m = wid * 16 + (lane >> 2);      // rows m and m+8
#pragma unroll
    for (int ni = 0; ni < 4; ni++) {
        int r = r0 + ni * 8 + klane;
        *(float2*)(part + (size_t)m * R + r) = make_float2(acc[ni][0], acc[ni][1]);
        *(float2*)(part + (size_t)(m + 8) * R + r) = make_float2(acc[ni][2], acc[ni][3]);
    }
}

// ---------------- reduce: sum parts + bias + PReLU -> fp16 activations ---------
template<int SEL, int NP>
__global__ void reduce_prelu_kernel(const float* __restrict__ bias,
                                    const float* __restrict__ alpha)
{
    const int idx4 = (blockIdx.x * blockDim.x + threadIdx.x) * 4;  // over 128*8192
    const int r = idx4 & (2 * NFEAT - 1);
    float4 v = *(const float4*)(g_part + idx4);
#pragma unroll
    for (int p = 1; p < NP; p++) {
        float4 u = *(const float4*)(g_part + (size_t)p * (BATCH * 2 * NFEAT) + idx4);
        v.x += u.x; v.y += u.y; v.z += u.z; v.w += u.w;
    }
    const float4 bv = *(const float4*)(bias + r);
    const float4 av = *(const float4*)(alpha + r);
    v.x += bv.x; v.y += bv.y; v.z += bv.z; v.w += bv.w;
    v.x = (v.x > 0.f) ? v.x : av.x * v.x;
    v.y = (v.y > 0.f) ? v.y : av.y * v.y;
    v.z = (v.z > 0.f) ? v.z : av.z * v.z;
    v.w = (v.w > 0.f) ? v.w : av.w * v.w;
    half2 lo = __floats2half2_rn(v.x, v.y);
    half2 hi = __floats2half2_rn(v.z, v.w);
    uint2 pk;
    pk.x = *(uint32_t*)&lo; pk.y = *(uint32_t*)&hi;
    half* act = (SEL == 0) ? (half*)g_act0_raw : (half*)g_act1_raw;
    *(uint2*)(act + idx4) = pk;
}

// ---------------- L2 final: sum parts + bias, sigmoid, unfold scatter ----------
__global__ void l2_final_kernel(const float* __restrict__ bias, float* __restrict__ out) {
    int idx = blockIdx.x * blockDim.x + threadIdx.x;   // 128*4096
    int r = idx & (NFEAT - 1);
    int m = idx >> 12;
    float v = g_part[idx]
            + g_part[(size_t)1 * (BATCH * 2 * NFEAT) + idx]
            + g_part[(size_t)2 * (BATCH * 2 * NFEAT) + idx]
            + g_part[(size_t)3 * (BATCH * 2 * NFEAT) + idx]
            + __ldg(bias + r);
    float g = (r == 0) ? 0.5f : 1.f / (1.f + __expf(-v));
    out[(m << 12) + perm_site(r)] = g;
}

// ---------------- launcher ------------------------------------------------------
extern "C" void kernel_launch(void* const* d_in, const int* in_sizes, int n_in,
                              void* d_out, int out_size) {
    const float* x  = (const float*)d_in[0];
    const float* W0 = (const float*)d_in[1];
    const float* b0 = (const float*)d_in[2];
    const float* a1 = (const float*)d_in[3];
    const float* W1 = (const float*)d_in[4];
    const float* b1 = (const float*)d_in[5];
    const float* a2 = (const float*)d_in[6];
    const float* W2 = (const float*)d_in[7];
    const float* b2 = (const float*)d_in[8];
    float* out = (float*)d_out;

    cudaFuncSetAttribute(mma_kernel<1, 2, true,  0>, cudaFuncAttributeMaxDynamicSharedMemorySize, SMEM_TOTAL);
    cudaFuncSetAttribute(mma_kernel<2, 2, false, 1>, cudaFuncAttributeMaxDynamicSharedMemorySize, SMEM_TOTAL);
    cudaFuncSetAttribute(mma_kernel<2, 2, false, 2>, cudaFuncAttributeMaxDynamicSharedMemorySize, SMEM_TOTAL);

    gather_kernel<<<(BATCH * NFEAT) / 256, 256>>>(x);

    // L0: exclusive mask, C=4096 split into 2x2048 -> 2 partials
    mma_kernel<1, 2, true,  0><<<512, 256, SMEM_TOTAL>>>(W0);
    reduce_prelu_kernel<0, 2><<<(BATCH * 2 * NFEAT) / 1024, 256>>>(b0, a1);
    // L1: inclusive mask, C=8192 split into 4x2048 -> 4 partials
    mma_kernel<2, 2, false, 1><<<1024, 256, SMEM_TOTAL>>>(W1);
    reduce_prelu_kernel<1, 4><<<(BATCH * 2 * NFEAT) / 1024, 256>>>(b1, a2);
    // L2: inclusive mask, C=8192 split into 4x2048 -> 4 partials
    mma_kernel<2, 2, false, 2><<<512, 256, SMEM_TOTAL>>>(W2);
    // L2 reduce: sum + bias, sigmoid, xhat mask/bias, unfold scatter
    l2_final_kernel<<<(BATCH * NFEAT) / 256, 256>>>(b2, out);
}